// round 5
// baseline (speedup 1.0000x reference)
#include <cuda_runtime.h>
#include <cstdint>
#include <math.h>

// ---------------------------------------------------------------- constants
#define N_PIX     8192
#define N_TOK     8
#define DIM       512
#define INNER     512
#define INNER3    1536
#define SCALE_F   0.125f
#define M_ROWS    65536

// GEMM tiling
#define BM     128
#define BN     128
#define BK     32
#define STAGES 3
#define TK     (DIM / BK)              // 16 K-tiles
#define APITCH 36                      // 36*4=144B rows (16B aligned, banks ok)
#define TILE_FLOATS (128 * APITCH)
#define STAGE_FLOATS (2 * TILE_FLOATS)
#define GEMM_SMEM (STAGES * STAGE_FLOATS * 4)   // 110592 B

#define QPITCH 516

// Scratch. All GEMM operand arrays use k-permuted layout within each
// 32-float k-block: slot(k) = (k%4)*8 + k/4.
__device__ float g_qkv[(size_t)M_ROWS * INNER3];   // normal layout
__device__ float g_att[(size_t)M_ROWS * INNER];    // permuted (via attn passthrough)
__device__ float g_xtf[(size_t)M_ROWS * DIM];      // permuted + tf32-rounded
__device__ float g_wqkvT[(size_t)INNER3 * DIM];    // K-major, permuted, rounded
__device__ float g_woutT[(size_t)INNER * DIM];     // K-major, permuted, rounded

// ---------------------------------------------------------------- helpers
__device__ __forceinline__ uint32_t smem_u32(const void* p) {
    uint32_t a;
    asm("{ .reg .u64 t; cvta.to.shared.u64 t, %1; cvt.u32.u64 %0, t; }"
        : "=r"(a) : "l"(p));
    return a;
}
__device__ __forceinline__ void cp16(uint32_t dst, const void* src) {
    asm volatile("cp.async.cg.shared.global [%0], [%1], 16;"
                 :: "r"(dst), "l"(src));
}
__device__ __forceinline__ void cp_commit() {
    asm volatile("cp.async.commit_group;" ::: "memory");
}
template <int N> __device__ __forceinline__ void cp_wait() {
    asm volatile("cp.async.wait_group %0;" :: "n"(N) : "memory");
}
__device__ __forceinline__ uint32_t f2tf(float f) {
    uint32_t u;
    asm("cvt.rna.tf32.f32 %0, %1;" : "=r"(u) : "f"(f));
    return u;
}
__device__ __forceinline__ float rtf(float f) {
    return __uint_as_float(f2tf(f));
}
__device__ __forceinline__ void mma_tf32(float* c, uint32_t a0, uint32_t a1,
                                         uint32_t a2, uint32_t a3,
                                         uint32_t b0, uint32_t b1) {
    asm volatile(
        "mma.sync.aligned.m16n8k8.row.col.f32.tf32.tf32.f32 "
        "{%0,%1,%2,%3}, {%4,%5,%6,%7}, {%8,%9}, {%0,%1,%2,%3};"
        : "+f"(c[0]), "+f"(c[1]), "+f"(c[2]), "+f"(c[3])
        : "r"(a0), "r"(a1), "r"(a2), "r"(a3), "r"(b0), "r"(b1));
}

// ---------------------------------------------------------------- tf32 GEMM
// Operands pre-rounded AND k-permuted. Fragment loads are LDS.128:
// thread (g,tig)'s 8 k-values per row live at slots [tig*8 .. tig*8+7].
template <bool BIAS>
__global__ void __launch_bounds__(256, 2)
gemm_tf32(const float* __restrict__ A, const float* __restrict__ Bt,
          const float* __restrict__ bias, float* __restrict__ C, int Ncols)
{
    extern __shared__ float sh[];
    const int tid  = threadIdx.x;
    const int wid  = tid >> 5, lane = tid & 31;
    const int g    = lane >> 2, tig = lane & 3;
    const int wm   = (wid >> 2) * 64;
    const int wn   = (wid & 3) * 32;
    const int bm   = blockIdx.y * BM;
    const int bn   = blockIdx.x * BN;
    const uint32_t sbase = smem_u32(sh);

    float c[4][4][4];
#pragma unroll
    for (int i = 0; i < 4; i++)
#pragma unroll
        for (int j = 0; j < 4; j++)
#pragma unroll
            for (int q = 0; q < 4; q++) c[i][j][q] = 0.f;

    auto load_tile = [&](int t, int s) {
        uint32_t st = sbase + (uint32_t)(s * STAGE_FLOATS * 4);
        const float* Ab = A + (size_t)bm * DIM + t * BK;
#pragma unroll
        for (int i = 0; i < 4; i++) {
            int id = tid + i * 256;
            int r = id >> 3, ck = id & 7;
            cp16(st + (uint32_t)(r * APITCH + ck * 4) * 4,
                 Ab + (size_t)r * DIM + ck * 4);
        }
        uint32_t stB = st + (uint32_t)TILE_FLOATS * 4;
        const float* Bb = Bt + (size_t)bn * DIM + t * BK;
#pragma unroll
        for (int i = 0; i < 4; i++) {
            int id = tid + i * 256;
            int r = id >> 3, ck = id & 7;
            cp16(stB + (uint32_t)(r * APITCH + ck * 4) * 4,
                 Bb + (size_t)r * DIM + ck * 4);
        }
    };

    load_tile(0, 0); cp_commit();
    load_tile(1, 1); cp_commit();

    for (int t = 0; t < TK; t++) {
        cp_wait<1>();
        __syncthreads();
        if (t + 2 < TK) { load_tile(t + 2, (t + 2) % STAGES); cp_commit(); }

        const float* As = sh + (size_t)(t % STAGES) * STAGE_FLOATS;
        const float* Bs = As + TILE_FLOATS;

        // 2 batches; batch h covers ks = 2h, 2h+1 (elements (0,1) / (2,3))
#pragma unroll
        for (int h = 0; h < 2; h++) {
            uint4 aLo[4], aHi[4], bFr[4];
#pragma unroll
            for (int mt = 0; mt < 4; mt++) {
                const float* ap = As + (wm + mt * 16 + g) * APITCH + tig * 8 + h * 4;
                aLo[mt] = *reinterpret_cast<const uint4*>(ap);
                aHi[mt] = *reinterpret_cast<const uint4*>(ap + 8 * APITCH);
            }
#pragma unroll
            for (int nt = 0; nt < 4; nt++) {
                const float* bp = Bs + (wn + nt * 8 + g) * APITCH + tig * 8 + h * 4;
                bFr[nt] = *reinterpret_cast<const uint4*>(bp);
            }
#pragma unroll
            for (int k2 = 0; k2 < 2; k2++) {
#pragma unroll
                for (int mt = 0; mt < 4; mt++) {
                    const uint32_t* al = reinterpret_cast<const uint32_t*>(&aLo[mt]);
                    const uint32_t* ah = reinterpret_cast<const uint32_t*>(&aHi[mt]);
#pragma unroll
                    for (int nt = 0; nt < 4; nt++) {
                        const uint32_t* bb = reinterpret_cast<const uint32_t*>(&bFr[nt]);
                        mma_tf32(c[mt][nt],
                                 al[2 * k2], ah[2 * k2],
                                 al[2 * k2 + 1], ah[2 * k2 + 1],
                                 bb[2 * k2], bb[2 * k2 + 1]);
                    }
                }
            }
        }
        __syncthreads();
    }

#pragma unroll
    for (int mt = 0; mt < 4; mt++) {
#pragma unroll
        for (int nt = 0; nt < 4; nt++) {
            int col = bn + wn + nt * 8 + 2 * tig;
            float b0 = 0.f, b1 = 0.f;
            if (BIAS) { b0 = bias[col]; b1 = bias[col + 1]; }
            int r0 = bm + wm + mt * 16 + g;
            float2 v0 = make_float2(c[mt][nt][0] + b0, c[mt][nt][1] + b1);
            float2 v1 = make_float2(c[mt][nt][2] + b0, c[mt][nt][3] + b1);
            *reinterpret_cast<float2*>(C + (size_t)r0 * Ncols + col) = v0;
            *reinterpret_cast<float2*>(C + (size_t)(r0 + 8) * Ncols + col) = v1;
        }
    }
}

// ---------------------------------------------------------------- pre-round + permute
// in: [M][512] normal; out: [M][512] tf32-rounded, k-permuted per 32-block.
__global__ void __launch_bounds__(256)
round_kernel(const float* __restrict__ in, float* __restrict__ out, size_t n4)
{
    size_t i = (size_t)blockIdx.x * blockDim.x + threadIdx.x;
    if (i >= n4) return;
    float4 v = reinterpret_cast<const float4*>(in)[i];
    size_t row = i >> 7;                 // 128 float4 per 512-float row
    int u  = (int)(i & 127);
    int b  = u >> 3, u8 = u & 7;
    float* o = out + row * DIM + b * 32 + u8;
    o[0]  = rtf(v.x);
    o[8]  = rtf(v.y);
    o[16] = rtf(v.z);
    o[24] = rtf(v.w);
}

// ---------------------------------------------------------------- transpose (+round +permute)
__global__ void __launch_bounds__(256)
transpose_kernel(const float* __restrict__ in, float* __restrict__ out,
                 int R, int Ccols)
{
    __shared__ float tile[32][33];
    int c0 = blockIdx.x * 32, r0 = blockIdx.y * 32;   // r0 = k-block base (mult of 32)
    int tx = threadIdx.x & 31, ty = threadIdx.x >> 5;
    for (int i = ty; i < 32; i += 8)
        tile[i][tx] = rtf(in[(size_t)(r0 + i) * Ccols + c0 + tx]);
    __syncthreads();
    for (int i = ty; i < 32; i += 8) {
        int slot = (tx & 3) * 8 + (tx >> 2);          // permute k within block
        out[(size_t)(c0 + i) * R + r0 + slot] = tile[tx][i];
    }
}

// ---------------------------------------------------------------- attention
// q/k/v stored into smem in PERMUTED k-layout (dots invariant under the
// permutation; v/out pass it through so g_att lands permuted for GEMM2).
__global__ void __launch_bounds__(256)
attn_kernel(const float* __restrict__ qkv, const float* __restrict__ mask,
            float* __restrict__ out)
{
    extern __shared__ float sh[];
    float* sq = sh;
    float* sk = sh + 8 * QPITCH;
    float* sv = sh + 16 * QPITCH;
    float* sd = sh + 24 * QPITCH;

    const int p   = blockIdx.x;
    const int tid = threadIdx.x;
    const float* base = qkv + (size_t)p * N_TOK * INNER3;

    for (int s = tid; s < 3072; s += 256) {
        int row = s / 384;
        int c4  = s % 384;
        float4 v = *reinterpret_cast<const float4*>(base + (size_t)row * INNER3 + c4 * 4);
        int col = c4 * 4;
        float* dst; int cc;
        if (col < 512)       { dst = sq + row * QPITCH; cc = col; }
        else if (col < 1024) { dst = sk + row * QPITCH; cc = col - 512; }
        else                 { dst = sv + row * QPITCH; cc = col - 1024; }
        int b = cc >> 5, u8 = (cc & 31) >> 2;
        float* o = dst + b * 32 + u8;
        o[0] = v.x; o[8] = v.y; o[16] = v.z; o[24] = v.w;
    }
    __syncthreads();

    for (int s = tid; s < 512; s += 256) {
        int h = s >> 6, i = (s >> 3) & 7, j = s & 7;
        const float4* qp = reinterpret_cast<const float4*>(&sq[i * QPITCH + h * 64]);
        const float4* kp = reinterpret_cast<const float4*>(&sk[j * QPITCH + h * 64]);
        float acc = 0.f;
#pragma unroll
        for (int d = 0; d < 16; d++) {
            float4 a = qp[d], b = kp[d];
            acc += a.x * b.x + a.y * b.y + a.z * b.z + a.w * b.w;
        }
        float m = mask[(size_t)p * 64 + i * 8 + j];
        sd[(h * 8 + i) * 8 + j] = acc * SCALE_F * m;
    }
    __syncthreads();

    if (tid < 64) {
        int h = tid >> 3, i = tid & 7;
        float* row = &sd[(h * 8 + i) * 8];
        float mx = row[0];
#pragma unroll
        for (int j = 1; j < 8; j++) mx = fmaxf(mx, row[j]);
        float e[8], sum = 0.f;
#pragma unroll
        for (int j = 0; j < 8; j++) { e[j] = __expf(row[j] - mx); sum += e[j]; }
        float inv = 1.f / sum;
#pragma unroll
        for (int j = 0; j < 8; j++) row[j] = e[j] * inv;
    }
    __syncthreads();

    // pass-through: permuted sv columns -> permuted out columns
    float* ob = out + (size_t)p * N_TOK * INNER;
    for (int s = tid; s < 1024; s += 256) {
        int i   = s >> 7;
        int c4  = s & 127;
        int col = c4 * 4;
        int h   = col >> 6;       // permutation stays within 32-blocks -> head ok
        float4 acc = make_float4(0.f, 0.f, 0.f, 0.f);
#pragma unroll
        for (int j = 0; j < 8; j++) {
            float a = sd[(h * 8 + i) * 8 + j];
            float4 vv = *reinterpret_cast<const float4*>(&sv[j * QPITCH + col]);
            acc.x = fmaf(a, vv.x, acc.x);
            acc.y = fmaf(a, vv.y, acc.y);
            acc.z = fmaf(a, vv.z, acc.z);
            acc.w = fmaf(a, vv.w, acc.w);
        }
        acc.x = rtf(acc.x); acc.y = rtf(acc.y);
        acc.z = rtf(acc.z); acc.w = rtf(acc.w);
        *reinterpret_cast<float4*>(ob + (size_t)i * INNER + col) = acc;
    }
}

// ---------------------------------------------------------------- launch
extern "C" void kernel_launch(void* const* d_in, const int* in_sizes, int n_in,
                              void* d_out, int out_size)
{
    (void)in_sizes; (void)n_in; (void)out_size;
    const float* x     = (const float*)d_in[0];
    const float* mask  = (const float*)d_in[1];
    const float* w_qkv = (const float*)d_in[2];
    const float* w_out = (const float*)d_in[3];
    const float* b_out = (const float*)d_in[4];
    float* out = (float*)d_out;

    float *qkv_p, *att_p, *xtf_p, *wqkvT_p, *woutT_p;
    cudaGetSymbolAddress((void**)&qkv_p, g_qkv);
    cudaGetSymbolAddress((void**)&att_p, g_att);
    cudaGetSymbolAddress((void**)&xtf_p, g_xtf);
    cudaGetSymbolAddress((void**)&wqkvT_p, g_wqkvT);
    cudaGetSymbolAddress((void**)&woutT_p, g_woutT);

    cudaFuncSetAttribute(gemm_tf32<false>,
                         cudaFuncAttributeMaxDynamicSharedMemorySize, GEMM_SMEM);
    cudaFuncSetAttribute(gemm_tf32<true>,
                         cudaFuncAttributeMaxDynamicSharedMemorySize, GEMM_SMEM);
    const int ATTN_SMEM = (24 * QPITCH + 512) * 4;
    cudaFuncSetAttribute(attn_kernel,
                         cudaFuncAttributeMaxDynamicSharedMemorySize, ATTN_SMEM);

    const size_t n4 = (size_t)M_ROWS * DIM / 4;
    round_kernel<<<(unsigned)((n4 + 255) / 256), 256>>>(x, xtf_p, n4);
    transpose_kernel<<<dim3(INNER3 / 32, DIM / 32), 256>>>(w_qkv, wqkvT_p, DIM, INNER3);
    transpose_kernel<<<dim3(INNER  / 32, DIM / 32), 256>>>(w_out, woutT_p, DIM, INNER);

    gemm_tf32<false><<<dim3(INNER3 / BN, M_ROWS / BM), 256, GEMM_SMEM>>>(
        xtf_p, wqkvT_p, nullptr, qkv_p, INNER3);
    attn_kernel<<<N_PIX, 256, ATTN_SMEM>>>(qkv_p, mask, att_p);
    gemm_tf32<true><<<dim3(INNER / BN, M_ROWS / BM), 256, GEMM_SMEM>>>(
        att_p, woutT_p, b_out, out, INNER);
}

// round 6
// speedup vs baseline: 1.0876x; 1.0876x over previous
#include <cuda_runtime.h>
#include <cstdint>
#include <math.h>

// ---------------------------------------------------------------- constants
#define N_PIX     8192
#define N_TOK     8
#define DIM       512
#define INNER     512
#define INNER3    1536
#define SCALE_F   0.125f
#define M_ROWS    65536

// GEMM tiling
#define BM     128
#define BN     128
#define BK     32
#define STAGES 3
#define TK     (DIM / BK)              // 16 K-tiles
#define APITCH 36                      // scalar frag loads hit all 32 banks
#define TILE_FLOATS (128 * APITCH)
#define STAGE_FLOATS (2 * TILE_FLOATS)
#define GEMM_SMEM (STAGES * STAGE_FLOATS * 4)   // 110592 B

#define QPITCH 516

// Scratch (__device__ globals per allocation rules)
__device__ float g_qkv[(size_t)M_ROWS * INNER3];
__device__ float g_att[(size_t)M_ROWS * INNER];    // tf32-rounded
__device__ float g_xtf[(size_t)M_ROWS * DIM];      // tf32-rounded x
__device__ float g_wqkvT[(size_t)INNER3 * DIM];    // K-major, rounded
__device__ float g_woutT[(size_t)INNER * DIM];     // K-major, rounded

// ---------------------------------------------------------------- helpers
__device__ __forceinline__ uint32_t smem_u32(const void* p) {
    uint32_t a;
    asm("{ .reg .u64 t; cvta.to.shared.u64 t, %1; cvt.u32.u64 %0, t; }"
        : "=r"(a) : "l"(p));
    return a;
}
__device__ __forceinline__ void cp16(uint32_t dst, const void* src) {
    asm volatile("cp.async.cg.shared.global [%0], [%1], 16;"
                 :: "r"(dst), "l"(src));
}
__device__ __forceinline__ void cp_commit() {
    asm volatile("cp.async.commit_group;" ::: "memory");
}
template <int N> __device__ __forceinline__ void cp_wait() {
    asm volatile("cp.async.wait_group %0;" :: "n"(N) : "memory");
}
__device__ __forceinline__ uint32_t f2tf(float f) {
    uint32_t u;
    asm("cvt.rna.tf32.f32 %0, %1;" : "=r"(u) : "f"(f));
    return u;
}
__device__ __forceinline__ float rtf(float f) {
    return __uint_as_float(f2tf(f));
}
__device__ __forceinline__ void mma_tf32(float* c, uint32_t a0, uint32_t a1,
                                         uint32_t a2, uint32_t a3,
                                         uint32_t b0, uint32_t b1) {
    asm volatile(
        "mma.sync.aligned.m16n8k8.row.col.f32.tf32.tf32.f32 "
        "{%0,%1,%2,%3}, {%4,%5,%6,%7}, {%8,%9}, {%0,%1,%2,%3};"
        : "+f"(c[0]), "+f"(c[1]), "+f"(c[2]), "+f"(c[3])
        : "r"(a0), "r"(a1), "r"(a2), "r"(a3), "r"(b0), "r"(b1));
}

// fragment set for one ks chunk (k8): 16 A regs + 8 B regs
struct Frag {
    uint32_t a[4][4];
    uint32_t b[4][2];
};

// all offsets compile-time immediates off (ap, bp)
__device__ __forceinline__ void load_frag(Frag& f, const float* ap,
                                          const float* bp, int ks)
{
    const int k0 = ks * 8;
#pragma unroll
    for (int mt = 0; mt < 4; mt++) {
        const float* p = ap + mt * (16 * APITCH) + k0;
        f.a[mt][0] = __float_as_uint(p[0]);
        f.a[mt][1] = __float_as_uint(p[8 * APITCH]);
        f.a[mt][2] = __float_as_uint(p[4]);
        f.a[mt][3] = __float_as_uint(p[8 * APITCH + 4]);
    }
#pragma unroll
    for (int nt = 0; nt < 4; nt++) {
        const float* p = bp + nt * (8 * APITCH) + k0;
        f.b[nt][0] = __float_as_uint(p[0]);
        f.b[nt][1] = __float_as_uint(p[4]);
    }
}

__device__ __forceinline__ void mma_frag(float c[4][4][4], const Frag& f)
{
#pragma unroll
    for (int mt = 0; mt < 4; mt++)
#pragma unroll
        for (int nt = 0; nt < 4; nt++)
            mma_tf32(c[mt][nt], f.a[mt][0], f.a[mt][1], f.a[mt][2], f.a[mt][3],
                     f.b[nt][0], f.b[nt][1]);
}

// ---------------------------------------------------------------- tf32 GEMM
// Pre-rounded operands; one barrier per K-tile; ks-double-buffered fragments.
template <bool BIAS>
__global__ void __launch_bounds__(256, 2)
gemm_tf32(const float* __restrict__ A, const float* __restrict__ Bt,
          const float* __restrict__ bias, float* __restrict__ C, int Ncols)
{
    extern __shared__ float sh[];
    const int tid  = threadIdx.x;
    const int wid  = tid >> 5, lane = tid & 31;
    const int g    = lane >> 2, tig = lane & 3;
    const int wm   = (wid >> 2) * 64;
    const int wn   = (wid & 3) * 32;
    const int bm   = blockIdx.y * BM;
    const int bn   = blockIdx.x * BN;
    const uint32_t sbase = smem_u32(sh);

    const int aBase = (wm + g) * APITCH + tig;
    const int bBase = (wn + g) * APITCH + tig;

    float c[4][4][4];
#pragma unroll
    for (int i = 0; i < 4; i++)
#pragma unroll
        for (int j = 0; j < 4; j++)
#pragma unroll
            for (int q = 0; q < 4; q++) c[i][j][q] = 0.f;

    auto load_tile = [&](int t, int s) {
        uint32_t st = sbase + (uint32_t)(s * STAGE_FLOATS * 4);
        const float* Ab = A + (size_t)bm * DIM + t * BK;
#pragma unroll
        for (int i = 0; i < 4; i++) {
            int id = tid + i * 256;
            int r = id >> 3, ck = id & 7;
            cp16(st + (uint32_t)(r * APITCH + ck * 4) * 4,
                 Ab + (size_t)r * DIM + ck * 4);
        }
        uint32_t stB = st + (uint32_t)TILE_FLOATS * 4;
        const float* Bb = Bt + (size_t)bn * DIM + t * BK;
#pragma unroll
        for (int i = 0; i < 4; i++) {
            int id = tid + i * 256;
            int r = id >> 3, ck = id & 7;
            cp16(stB + (uint32_t)(r * APITCH + ck * 4) * 4,
                 Bb + (size_t)r * DIM + ck * 4);
        }
    };

    load_tile(0, 0); cp_commit();
    load_tile(1, 1); cp_commit();

    for (int t = 0; t < TK; t++) {
        cp_wait<1>();
        __syncthreads();               // single barrier per tile:
                                       // orders compute(t-1) before stage reuse
                                       // AND makes tile-t loads visible
        if (t + 2 < TK) load_tile(t + 2, (t + 2) % STAGES);
        cp_commit();                   // unconditional (empty groups keep count)

        const float* As = sh + (size_t)(t % STAGES) * STAGE_FLOATS;
        const float* ap = As + aBase;
        const float* bp = As + TILE_FLOATS + bBase;

        Frag f0, f1;
        load_frag(f0, ap, bp, 0);
        load_frag(f1, ap, bp, 1);
        mma_frag(c, f0);
        load_frag(f0, ap, bp, 2);
        mma_frag(c, f1);
        load_frag(f1, ap, bp, 3);
        mma_frag(c, f0);
        mma_frag(c, f1);
    }

#pragma unroll
    for (int mt = 0; mt < 4; mt++) {
#pragma unroll
        for (int nt = 0; nt < 4; nt++) {
            int col = bn + wn + nt * 8 + 2 * tig;
            float b0 = 0.f, b1 = 0.f;
            if (BIAS) { b0 = bias[col]; b1 = bias[col + 1]; }
            int r0 = bm + wm + mt * 16 + g;
            float2 v0 = make_float2(c[mt][nt][0] + b0, c[mt][nt][1] + b1);
            float2 v1 = make_float2(c[mt][nt][2] + b0, c[mt][nt][3] + b1);
            *reinterpret_cast<float2*>(C + (size_t)r0 * Ncols + col) = v0;
            *reinterpret_cast<float2*>(C + (size_t)(r0 + 8) * Ncols + col) = v1;
        }
    }
}

// ---------------------------------------------------------------- pre-round
__global__ void __launch_bounds__(256)
round_kernel(const float* __restrict__ in, float* __restrict__ out, size_t n4)
{
    size_t i = (size_t)blockIdx.x * blockDim.x + threadIdx.x;
    if (i >= n4) return;
    float4 v = reinterpret_cast<const float4*>(in)[i];
    v.x = rtf(v.x); v.y = rtf(v.y); v.z = rtf(v.z); v.w = rtf(v.w);
    reinterpret_cast<float4*>(out)[i] = v;
}

// ---------------------------------------------------------------- transpose (+round)
__global__ void __launch_bounds__(256)
transpose_kernel(const float* __restrict__ in, float* __restrict__ out,
                 int R, int Ccols)
{
    __shared__ float tile[32][33];
    int c0 = blockIdx.x * 32, r0 = blockIdx.y * 32;
    int tx = threadIdx.x & 31, ty = threadIdx.x >> 5;
    for (int i = ty; i < 32; i += 8)
        tile[i][tx] = rtf(in[(size_t)(r0 + i) * Ccols + c0 + tx]);
    __syncthreads();
    for (int i = ty; i < 32; i += 8)
        out[(size_t)(c0 + i) * R + r0 + tx] = tile[tx][i];
}

// ---------------------------------------------------------------- attention
__global__ void __launch_bounds__(256)
attn_kernel(const float* __restrict__ qkv, const float* __restrict__ mask,
            float* __restrict__ out)
{
    extern __shared__ float sh[];
    float* sq = sh;
    float* sk = sh + 8 * QPITCH;
    float* sv = sh + 16 * QPITCH;
    float* sd = sh + 24 * QPITCH;

    const int p   = blockIdx.x;
    const int tid = threadIdx.x;
    const float* base = qkv + (size_t)p * N_TOK * INNER3;

    for (int s = tid; s < 3072; s += 256) {
        int row = s / 384;
        int c4  = s % 384;
        float4 v = *reinterpret_cast<const float4*>(base + (size_t)row * INNER3 + c4 * 4);
        int col = c4 * 4;
        if (col < 512)
            *reinterpret_cast<float4*>(&sq[row * QPITCH + col]) = v;
        else if (col < 1024)
            *reinterpret_cast<float4*>(&sk[row * QPITCH + col - 512]) = v;
        else
            *reinterpret_cast<float4*>(&sv[row * QPITCH + col - 1024]) = v;
    }
    __syncthreads();

    for (int s = tid; s < 512; s += 256) {
        int h = s >> 6, i = (s >> 3) & 7, j = s & 7;
        const float4* qp = reinterpret_cast<const float4*>(&sq[i * QPITCH + h * 64]);
        const float4* kp = reinterpret_cast<const float4*>(&sk[j * QPITCH + h * 64]);
        float acc = 0.f;
#pragma unroll
        for (int d = 0; d < 16; d++) {
            float4 a = qp[d], b = kp[d];
            acc += a.x * b.x + a.y * b.y + a.z * b.z + a.w * b.w;
        }
        float m = mask[(size_t)p * 64 + i * 8 + j];
        sd[(h * 8 + i) * 8 + j] = acc * SCALE_F * m;
    }
    __syncthreads();

    if (tid < 64) {
        int h = tid >> 3, i = tid & 7;
        float* row = &sd[(h * 8 + i) * 8];
        float mx = row[0];
#pragma unroll
        for (int j = 1; j < 8; j++) mx = fmaxf(mx, row[j]);
        float e[8], sum = 0.f;
#pragma unroll
        for (int j = 0; j < 8; j++) { e[j] = __expf(row[j] - mx); sum += e[j]; }
        float inv = 1.f / sum;
#pragma unroll
        for (int j = 0; j < 8; j++) row[j] = e[j] * inv;
    }
    __syncthreads();

    float* ob = out + (size_t)p * N_TOK * INNER;
    for (int s = tid; s < 1024; s += 256) {
        int i   = s >> 7;
        int c4  = s & 127;
        int col = c4 * 4;
        int h   = col >> 6;
        float4 acc = make_float4(0.f, 0.f, 0.f, 0.f);
#pragma unroll
        for (int j = 0; j < 8; j++) {
            float a = sd[(h * 8 + i) * 8 + j];
            float4 vv = *reinterpret_cast<const float4*>(&sv[j * QPITCH + col]);
            acc.x = fmaf(a, vv.x, acc.x);
            acc.y = fmaf(a, vv.y, acc.y);
            acc.z = fmaf(a, vv.z, acc.z);
            acc.w = fmaf(a, vv.w, acc.w);
        }
        acc.x = rtf(acc.x); acc.y = rtf(acc.y);
        acc.z = rtf(acc.z); acc.w = rtf(acc.w);
        *reinterpret_cast<float4*>(ob + (size_t)i * INNER + col) = acc;
    }
}

// ---------------------------------------------------------------- launch
extern "C" void kernel_launch(void* const* d_in, const int* in_sizes, int n_in,
                              void* d_out, int out_size)
{
    (void)in_sizes; (void)n_in; (void)out_size;
    const float* x     = (const float*)d_in[0];
    const float* mask  = (const float*)d_in[1];
    const float* w_qkv = (const float*)d_in[2];
    const float* w_out = (const float*)d_in[3];
    const float* b_out = (const float*)d_in[4];
    float* out = (float*)d_out;

    float *qkv_p, *att_p, *xtf_p, *wqkvT_p, *woutT_p;
    cudaGetSymbolAddress((void**)&qkv_p, g_qkv);
    cudaGetSymbolAddress((void**)&att_p, g_att);
    cudaGetSymbolAddress((void**)&xtf_p, g_xtf);
    cudaGetSymbolAddress((void**)&wqkvT_p, g_wqkvT);
    cudaGetSymbolAddress((void**)&woutT_p, g_woutT);

    cudaFuncSetAttribute(gemm_tf32<false>,
                         cudaFuncAttributeMaxDynamicSharedMemorySize, GEMM_SMEM);
    cudaFuncSetAttribute(gemm_tf32<true>,
                         cudaFuncAttributeMaxDynamicSharedMemorySize, GEMM_SMEM);
    const int ATTN_SMEM = (24 * QPITCH + 512) * 4;
    cudaFuncSetAttribute(attn_kernel,
                         cudaFuncAttributeMaxDynamicSharedMemorySize, ATTN_SMEM);

    const size_t n4 = (size_t)M_ROWS * DIM / 4;
    round_kernel<<<(unsigned)((n4 + 255) / 256), 256>>>(x, xtf_p, n4);
    transpose_kernel<<<dim3(INNER3 / 32, DIM / 32), 256>>>(w_qkv, wqkvT_p, DIM, INNER3);
    transpose_kernel<<<dim3(INNER  / 32, DIM / 32), 256>>>(w_out, woutT_p, DIM, INNER);

    gemm_tf32<false><<<dim3(INNER3 / BN, M_ROWS / BM), 256, GEMM_SMEM>>>(
        xtf_p, wqkvT_p, nullptr, qkv_p, INNER3);
    attn_kernel<<<N_PIX, 256, ATTN_SMEM>>>(qkv_p, mask, att_p);
    gemm_tf32<true><<<dim3(INNER / BN, M_ROWS / BM), 256, GEMM_SMEM>>>(
        att_p, woutT_p, b_out, out, INNER);
}

// round 8
// speedup vs baseline: 1.6024x; 1.4733x over previous
#include <cuda_runtime.h>
#include <cuda_fp16.h>
#include <cstdint>
#include <math.h>

// ---------------------------------------------------------------- constants
#define N_PIX     8192
#define N_TOK     8
#define DIM       512
#define INNER     512
#define INNER3    1536
#define SCALE_F   0.125f
#define M_ROWS    65536

// GEMM tiling (fp16 m16n8k16)
#define BM     128
#define BN     128
#define BK     32                       // halves of K per tile (2 k16 chunks)
#define STAGES 3
#define TK     (DIM / BK)               // 16 K-tiles
#define HPITCH 40                       // halves per smem row (80 B)
#define WPITCH 20                       // 32-bit words per row
#define TILE_BYTES  (128 * HPITCH * 2)  // 10240 B per operand
#define STAGE_BYTES (2 * TILE_BYTES)    // 20480 B
#define GEMM_SMEM   (STAGES * STAGE_BYTES)  // 61440 B

#define QPITCH 516

// Scratch (__device__ globals per allocation rules)
__device__ float  g_qkv[(size_t)M_ROWS * INNER3];   // fp32 (attn input)
__device__ __half g_att[(size_t)M_ROWS * INNER];    // fp16 (GEMM2 A operand)
__device__ __half g_xtf[(size_t)M_ROWS * DIM];      // fp16 x
__device__ __half g_wqkvT[(size_t)INNER3 * DIM];    // K-major fp16
__device__ __half g_woutT[(size_t)INNER * DIM];     // K-major fp16

// ---------------------------------------------------------------- helpers
__device__ __forceinline__ uint32_t smem_u32(const void* p) {
    uint32_t a;
    asm("{ .reg .u64 t; cvta.to.shared.u64 t, %1; cvt.u32.u64 %0, t; }"
        : "=r"(a) : "l"(p));
    return a;
}
__device__ __forceinline__ void cp16(uint32_t dst, const void* src) {
    asm volatile("cp.async.cg.shared.global [%0], [%1], 16;"
                 :: "r"(dst), "l"(src));
}
__device__ __forceinline__ void cp_commit() {
    asm volatile("cp.async.commit_group;" ::: "memory");
}
template <int N> __device__ __forceinline__ void cp_wait() {
    asm volatile("cp.async.wait_group %0;" :: "n"(N) : "memory");
}
__device__ __forceinline__ void mma_f16(float* c, uint32_t a0, uint32_t a1,
                                        uint32_t a2, uint32_t a3,
                                        uint32_t b0, uint32_t b1) {
    asm volatile(
        "mma.sync.aligned.m16n8k16.row.col.f32.f16.f16.f32 "
        "{%0,%1,%2,%3}, {%4,%5,%6,%7}, {%8,%9}, {%0,%1,%2,%3};"
        : "+f"(c[0]), "+f"(c[1]), "+f"(c[2]), "+f"(c[3])
        : "r"(a0), "r"(a1), "r"(a2), "r"(a3), "r"(b0), "r"(b1));
}
__device__ __forceinline__ uint32_t packh2(float x, float y) {
    __half2 h = __floats2half2_rn(x, y);
    return *reinterpret_cast<uint32_t*>(&h);
}

// ---------------------------------------------------------------- fp16 GEMM
// C[M, Ncols] = A[M,512] @ Bt[Ncols,512]^T (+bias), fp16 in / fp32 accum+out.
// 8 warps 2x4; warp tile 64x32; 2 k16 chunks per 32-half K-tile.
template <bool BIAS>
__global__ void __launch_bounds__(256, 2)
gemm_f16(const __half* __restrict__ A, const __half* __restrict__ Bt,
         const float* __restrict__ bias, float* __restrict__ C, int Ncols)
{
    extern __shared__ char smem[];
    const int tid  = threadIdx.x;
    const int wid  = tid >> 5, lane = tid & 31;
    const int g    = lane >> 2, tig = lane & 3;
    const int wm   = (wid >> 2) * 64;
    const int wn   = (wid & 3) * 32;
    const int bm   = blockIdx.y * BM;
    const int bn   = blockIdx.x * BN;
    const uint32_t sbase = smem_u32(smem);
    const uint32_t* shw = reinterpret_cast<const uint32_t*>(smem);

    float c[4][4][4];
#pragma unroll
    for (int i = 0; i < 4; i++)
#pragma unroll
        for (int j = 0; j < 4; j++)
#pragma unroll
            for (int q = 0; q < 4; q++) c[i][j][q] = 0.f;

    auto load_tile = [&](int t, int s) {
        uint32_t st = sbase + (uint32_t)(s * STAGE_BYTES);
        const __half* Ab = A + (size_t)bm * DIM + t * BK;
#pragma unroll
        for (int i = 0; i < 2; i++) {            // 512 chunks / 256 thr
            int id = tid + i * 256;
            int r = id >> 2, ck = id & 3;        // row, 8-half chunk
            cp16(st + (uint32_t)(r * HPITCH + ck * 8) * 2,
                 Ab + (size_t)r * DIM + ck * 8);
        }
        uint32_t stB = st + TILE_BYTES;
        const __half* Bb = Bt + (size_t)bn * DIM + t * BK;
#pragma unroll
        for (int i = 0; i < 2; i++) {
            int id = tid + i * 256;
            int r = id >> 2, ck = id & 3;
            cp16(stB + (uint32_t)(r * HPITCH + ck * 8) * 2,
                 Bb + (size_t)r * DIM + ck * 8);
        }
    };

    load_tile(0, 0); cp_commit();
    load_tile(1, 1); cp_commit();

    const int aBase = (wm + g) * WPITCH + tig;
    const int bBase = (wn + g) * WPITCH + tig;

    for (int t = 0; t < TK; t++) {
        cp_wait<1>();
        __syncthreads();
        if (t + 2 < TK) load_tile(t + 2, (t + 2) % STAGES);
        cp_commit();

        const uint32_t* Aw = shw + (size_t)(t % STAGES) * (STAGE_BYTES / 4);
        const uint32_t* Bw = Aw + TILE_BYTES / 4;
        const uint32_t* aw = Aw + aBase;
        const uint32_t* bw = Bw + bBase;

#pragma unroll
        for (int ch = 0; ch < 2; ch++) {          // k16 chunk
            const int ko = ch * 8;                // word offset within row
            uint32_t af[4][4], bf[4][2];
#pragma unroll
            for (int mt = 0; mt < 4; mt++) {
                const uint32_t* p = aw + mt * (16 * WPITCH) + ko;
                af[mt][0] = p[0];
                af[mt][1] = p[8 * WPITCH];
                af[mt][2] = p[4];
                af[mt][3] = p[8 * WPITCH + 4];
            }
#pragma unroll
            for (int nt = 0; nt < 4; nt++) {
                const uint32_t* p = bw + nt * (8 * WPITCH) + ko;
                bf[nt][0] = p[0];
                bf[nt][1] = p[4];
            }
#pragma unroll
            for (int mt = 0; mt < 4; mt++)
#pragma unroll
                for (int nt = 0; nt < 4; nt++)
                    mma_f16(c[mt][nt], af[mt][0], af[mt][1], af[mt][2],
                            af[mt][3], bf[nt][0], bf[nt][1]);
        }
        __syncthreads();
    }

#pragma unroll
    for (int mt = 0; mt < 4; mt++) {
#pragma unroll
        for (int nt = 0; nt < 4; nt++) {
            int col = bn + wn + nt * 8 + 2 * tig;
            float b0 = 0.f, b1 = 0.f;
            if (BIAS) { b0 = bias[col]; b1 = bias[col + 1]; }
            int r0 = bm + wm + mt * 16 + g;
            float2 v0 = make_float2(c[mt][nt][0] + b0, c[mt][nt][1] + b1);
            float2 v1 = make_float2(c[mt][nt][2] + b0, c[mt][nt][3] + b1);
            *reinterpret_cast<float2*>(C + (size_t)r0 * Ncols + col) = v0;
            *reinterpret_cast<float2*>(C + (size_t)(r0 + 8) * Ncols + col) = v1;
        }
    }
}

// ---------------------------------------------------------------- fp32 -> fp16
__global__ void __launch_bounds__(256)
tohalf_kernel(const float* __restrict__ in, __half* __restrict__ out, size_t n4)
{
    size_t i = (size_t)blockIdx.x * blockDim.x + threadIdx.x;
    if (i >= n4) return;
    float4 v = reinterpret_cast<const float4*>(in)[i];
    uint2 o;
    o.x = packh2(v.x, v.y);
    o.y = packh2(v.z, v.w);
    reinterpret_cast<uint2*>(out)[i] = o;
}

// ---------------------------------------------------------------- transpose (+fp16)
__global__ void __launch_bounds__(256)
transpose_kernel(const float* __restrict__ in, __half* __restrict__ out,
                 int R, int Ccols)
{
    __shared__ float tile[32][33];
    int c0 = blockIdx.x * 32, r0 = blockIdx.y * 32;
    int tx = threadIdx.x & 31, ty = threadIdx.x >> 5;
    for (int i = ty; i < 32; i += 8)
        tile[i][tx] = in[(size_t)(r0 + i) * Ccols + c0 + tx];
    __syncthreads();
    for (int i = ty; i < 32; i += 8)
        out[(size_t)(c0 + i) * R + r0 + tx] = __float2half_rn(tile[tx][i]);
}

// ---------------------------------------------------------------- attention
// reads fp32 qkv, computes fp32, writes fp16 att.
__global__ void __launch_bounds__(256)
attn_kernel(const float* __restrict__ qkv, const float* __restrict__ mask,
            __half* __restrict__ out)
{
    extern __shared__ float sh[];
    float* sq = sh;
    float* sk = sh + 8 * QPITCH;
    float* sv = sh + 16 * QPITCH;
    float* sd = sh + 24 * QPITCH;

    const int p   = blockIdx.x;
    const int tid = threadIdx.x;
    const float* base = qkv + (size_t)p * N_TOK * INNER3;

    for (int s = tid; s < 3072; s += 256) {
        int row = s / 384;
        int c4  = s % 384;
        float4 v = *reinterpret_cast<const float4*>(base + (size_t)row * INNER3 + c4 * 4);
        int col = c4 * 4;
        if (col < 512)
            *reinterpret_cast<float4*>(&sq[row * QPITCH + col]) = v;
        else if (col < 1024)
            *reinterpret_cast<float4*>(&sk[row * QPITCH + col - 512]) = v;
        else
            *reinterpret_cast<float4*>(&sv[row * QPITCH + col - 1024]) = v;
    }
    __syncthreads();

    for (int s = tid; s < 512; s += 256) {
        int h = s >> 6, i = (s >> 3) & 7, j = s & 7;
        const float4* qp = reinterpret_cast<const float4*>(&sq[i * QPITCH + h * 64]);
        const float4* kp = reinterpret_cast<const float4*>(&sk[j * QPITCH + h * 64]);
        float acc = 0.f;
#pragma unroll
        for (int d = 0; d < 16; d++) {
            float4 a = qp[d], b = kp[d];
            acc += a.x * b.x + a.y * b.y + a.z * b.z + a.w * b.w;
        }
        float m = mask[(size_t)p * 64 + i * 8 + j];
        sd[(h * 8 + i) * 8 + j] = acc * SCALE_F * m;
    }
    __syncthreads();

    if (tid < 64) {
        int h = tid >> 3, i = tid & 7;
        float* row = &sd[(h * 8 + i) * 8];
        float mx = row[0];
#pragma unroll
        for (int j = 1; j < 8; j++) mx = fmaxf(mx, row[j]);
        float e[8], sum = 0.f;
#pragma unroll
        for (int j = 0; j < 8; j++) { e[j] = __expf(row[j] - mx); sum += e[j]; }
        float inv = 1.f / sum;
#pragma unroll
        for (int j = 0; j < 8; j++) row[j] = e[j] * inv;
    }
    __syncthreads();

    __half* ob = out + (size_t)p * N_TOK * INNER;
    for (int s = tid; s < 1024; s += 256) {
        int i   = s >> 7;
        int c4  = s & 127;
        int col = c4 * 4;
        int h   = col >> 6;
        float4 acc = make_float4(0.f, 0.f, 0.f, 0.f);
#pragma unroll
        for (int j = 0; j < 8; j++) {
            float a = sd[(h * 8 + i) * 8 + j];
            float4 vv = *reinterpret_cast<const float4*>(&sv[j * QPITCH + col]);
            acc.x = fmaf(a, vv.x, acc.x);
            acc.y = fmaf(a, vv.y, acc.y);
            acc.z = fmaf(a, vv.z, acc.z);
            acc.w = fmaf(a, vv.w, acc.w);
        }
        uint2 o;
        o.x = packh2(acc.x, acc.y);
        o.y = packh2(acc.z, acc.w);
        *reinterpret_cast<uint2*>(ob + (size_t)i * INNER + col) = o;
    }
}

// ---------------------------------------------------------------- launch
extern "C" void kernel_launch(void* const* d_in, const int* in_sizes, int n_in,
                              void* d_out, int out_size)
{
    (void)in_sizes; (void)n_in; (void)out_size;
    const float* x     = (const float*)d_in[0];
    const float* mask  = (const float*)d_in[1];
    const float* w_qkv = (const float*)d_in[2];
    const float* w_out = (const float*)d_in[3];
    const float* b_out = (const float*)d_in[4];
    float* out = (float*)d_out;

    float *qkv_p;
    __half *att_p, *xtf_p, *wqkvT_p, *woutT_p;
    cudaGetSymbolAddress((void**)&qkv_p, g_qkv);
    cudaGetSymbolAddress((void**)&att_p, g_att);
    cudaGetSymbolAddress((void**)&xtf_p, g_xtf);
    cudaGetSymbolAddress((void**)&wqkvT_p, g_wqkvT);
    cudaGetSymbolAddress((void**)&woutT_p, g_woutT);

    cudaFuncSetAttribute(gemm_f16<false>,
                         cudaFuncAttributeMaxDynamicSharedMemorySize, GEMM_SMEM);
    cudaFuncSetAttribute(gemm_f16<true>,
                         cudaFuncAttributeMaxDynamicSharedMemorySize, GEMM_SMEM);
    const int ATTN_SMEM = (24 * QPITCH + 512) * 4;
    cudaFuncSetAttribute(attn_kernel,
                         cudaFuncAttributeMaxDynamicSharedMemorySize, ATTN_SMEM);

    const size_t n4 = (size_t)M_ROWS * DIM / 4;
    tohalf_kernel<<<(unsigned)((n4 + 255) / 256), 256>>>(x, xtf_p, n4);
    transpose_kernel<<<dim3(INNER3 / 32, DIM / 32), 256>>>(w_qkv, wqkvT_p, DIM, INNER3);
    transpose_kernel<<<dim3(INNER  / 32, DIM / 32), 256>>>(w_out, woutT_p, DIM, INNER);

    // 1) qkv = x @ w_qkv  (fp16 in, fp32 out)
    gemm_f16<false><<<dim3(INNER3 / BN, M_ROWS / BM), 256, GEMM_SMEM>>>(
        xtf_p, wqkvT_p, nullptr, qkv_p, INNER3);
    // 2) attention (fp32 in, fp16 out)
    attn_kernel<<<N_PIX, 256, ATTN_SMEM>>>(qkv_p, mask, att_p);
    // 3) out = att @ w_out + b_out
    gemm_f16<true><<<dim3(INNER / BN, M_ROWS / BM), 256, GEMM_SMEM>>>(
        att_p, woutT_p, b_out, out, INNER);
}

// round 9
// speedup vs baseline: 1.9462x; 1.2146x over previous
#include <cuda_runtime.h>
#include <cuda_fp16.h>
#include <cstdint>
#include <math.h>

// ---------------------------------------------------------------- constants
#define N_PIX     8192
#define N_TOK     8
#define DIM       512
#define INNER     512
#define INNER3    1536
#define SCALE_F   0.125f
#define M_ROWS    65536

// GEMM tiling (fp16 m16n8k16)
#define BM     128
#define BN     128
#define BK     32                       // halves of K per tile (2 k16 chunks)
#define STAGES 3
#define TK     (DIM / BK)               // 16 K-tiles
#define HPITCH 40                       // halves per smem row (80 B)
#define ROWB   80                       // bytes per row
#define TILE_BYTES  (128 * ROWB)        // 10240 B per operand
#define STAGE_BYTES (2 * TILE_BYTES)    // 20480 B
#define GEMM_SMEM   (STAGES * STAGE_BYTES)  // 61440 B

#define QPITCH 516

// Scratch (__device__ globals per allocation rules)
__device__ __half g_qkv[(size_t)M_ROWS * INNER3];   // fp16 qkv (~201 MB)
__device__ __half g_att[(size_t)M_ROWS * INNER];    // fp16 attn out
__device__ __half g_xtf[(size_t)M_ROWS * DIM];      // fp16 x
__device__ __half g_wqkvT[(size_t)INNER3 * DIM];    // K-major fp16
__device__ __half g_woutT[(size_t)INNER * DIM];     // K-major fp16

// ---------------------------------------------------------------- helpers
__device__ __forceinline__ uint32_t smem_u32(const void* p) {
    uint32_t a;
    asm("{ .reg .u64 t; cvta.to.shared.u64 t, %1; cvt.u32.u64 %0, t; }"
        : "=r"(a) : "l"(p));
    return a;
}
__device__ __forceinline__ void cp16(uint32_t dst, const void* src) {
    asm volatile("cp.async.cg.shared.global [%0], [%1], 16;"
                 :: "r"(dst), "l"(src));
}
__device__ __forceinline__ void cp_commit() {
    asm volatile("cp.async.commit_group;" ::: "memory");
}
template <int N> __device__ __forceinline__ void cp_wait() {
    asm volatile("cp.async.wait_group %0;" :: "n"(N) : "memory");
}
__device__ __forceinline__ void ldmx4(uint32_t* r, uint32_t addr) {
    asm volatile("ldmatrix.sync.aligned.m8n8.x4.shared.b16 {%0,%1,%2,%3}, [%4];"
                 : "=r"(r[0]), "=r"(r[1]), "=r"(r[2]), "=r"(r[3]) : "r"(addr));
}
__device__ __forceinline__ void mma_f16(float* c, uint32_t a0, uint32_t a1,
                                        uint32_t a2, uint32_t a3,
                                        uint32_t b0, uint32_t b1) {
    asm volatile(
        "mma.sync.aligned.m16n8k16.row.col.f32.f16.f16.f32 "
        "{%0,%1,%2,%3}, {%4,%5,%6,%7}, {%8,%9}, {%0,%1,%2,%3};"
        : "+f"(c[0]), "+f"(c[1]), "+f"(c[2]), "+f"(c[3])
        : "r"(a0), "r"(a1), "r"(a2), "r"(a3), "r"(b0), "r"(b1));
}
__device__ __forceinline__ uint32_t packh2(float x, float y) {
    __half2 h = __floats2half2_rn(x, y);
    return *reinterpret_cast<uint32_t*>(&h);
}

// ---------------------------------------------------------------- fp16 GEMM
// C[M, Ncols] = A[M,512] @ Bt[Ncols,512]^T (+bias). ldmatrix fragment loads.
template <bool BIAS, typename OutT>
__global__ void __launch_bounds__(256, 2)
gemm_f16(const __half* __restrict__ A, const __half* __restrict__ Bt,
         const float* __restrict__ bias, OutT* __restrict__ C, int Ncols)
{
    extern __shared__ char smem[];
    const int tid  = threadIdx.x;
    const int wid  = tid >> 5, lane = tid & 31;
    const int g    = lane >> 2, tig = lane & 3;
    const int wm   = (wid >> 2) * 64;
    const int wn   = (wid & 3) * 32;
    const int bm   = blockIdx.y * BM;
    const int bn   = blockIdx.x * BN;
    const uint32_t sbase = smem_u32(smem);

    // ldmatrix per-lane address components
    const int lm = lane >> 3, lr = lane & 7;         // matrix idx, row in matrix
    // A x4: m0=(rlo,klo) m1=(rhi,klo) m2=(rlo,khi) m3=(rhi,khi)
    const uint32_t aLane = (uint32_t)(((lm & 1) * 8 + lr) * ROWB + (lm >> 1) * 16);
    // B x4: m0=(n-lo8,klo) m1=(n-lo8,khi) m2=(n-hi8,klo) m3=(n-hi8,khi)
    const uint32_t bLane = (uint32_t)(((lm >> 1) * 8 + lr) * ROWB + (lm & 1) * 16);
    const uint32_t aBase = (uint32_t)(wm * ROWB) + aLane;
    const uint32_t bBase = (uint32_t)(TILE_BYTES + wn * ROWB) + bLane;

    float c[4][4][4];
#pragma unroll
    for (int i = 0; i < 4; i++)
#pragma unroll
        for (int j = 0; j < 4; j++)
#pragma unroll
            for (int q = 0; q < 4; q++) c[i][j][q] = 0.f;

    auto load_tile = [&](int t, int s) {
        uint32_t st = sbase + (uint32_t)(s * STAGE_BYTES);
        const __half* Ab = A + (size_t)bm * DIM + t * BK;
#pragma unroll
        for (int i = 0; i < 2; i++) {
            int id = tid + i * 256;
            int r = id >> 2, ck = id & 3;
            cp16(st + (uint32_t)(r * ROWB + ck * 16),
                 Ab + (size_t)r * DIM + ck * 8);
        }
        uint32_t stB = st + TILE_BYTES;
        const __half* Bb = Bt + (size_t)bn * DIM + t * BK;
#pragma unroll
        for (int i = 0; i < 2; i++) {
            int id = tid + i * 256;
            int r = id >> 2, ck = id & 3;
            cp16(stB + (uint32_t)(r * ROWB + ck * 16),
                 Bb + (size_t)r * DIM + ck * 8);
        }
    };

    load_tile(0, 0); cp_commit();
    load_tile(1, 1); cp_commit();

    for (int t = 0; t < TK; t++) {
        cp_wait<1>();
        __syncthreads();
        if (t + 2 < TK) load_tile(t + 2, (t + 2) % STAGES);
        cp_commit();

        const uint32_t stage = sbase + (uint32_t)((t % STAGES) * STAGE_BYTES);
        const uint32_t aAddr = stage + aBase;
        const uint32_t bAddr = stage + bBase;

#pragma unroll
        for (int ch = 0; ch < 2; ch++) {          // k16 chunk (32 B apart)
            const uint32_t ko = (uint32_t)(ch * 32);
            uint32_t af[4][4], bf[2][4];
#pragma unroll
            for (int mt = 0; mt < 4; mt++)
                ldmx4(af[mt], aAddr + (uint32_t)(mt * 16 * ROWB) + ko);
#pragma unroll
            for (int p = 0; p < 2; p++)           // nt pair (nt=2p, 2p+1)
                ldmx4(bf[p], bAddr + (uint32_t)(p * 16 * ROWB) + ko);
#pragma unroll
            for (int mt = 0; mt < 4; mt++)
#pragma unroll
                for (int nt = 0; nt < 4; nt++) {
                    const uint32_t* bb = &bf[nt >> 1][(nt & 1) * 2];
                    mma_f16(c[mt][nt], af[mt][0], af[mt][1], af[mt][2],
                            af[mt][3], bb[0], bb[1]);
                }
        }
        __syncthreads();
    }

#pragma unroll
    for (int mt = 0; mt < 4; mt++) {
#pragma unroll
        for (int nt = 0; nt < 4; nt++) {
            int col = bn + wn + nt * 8 + 2 * tig;
            float b0 = 0.f, b1 = 0.f;
            if (BIAS) { b0 = bias[col]; b1 = bias[col + 1]; }
            int r0 = bm + wm + mt * 16 + g;
            if (sizeof(OutT) == 2) {
                __half* Ch = reinterpret_cast<__half*>(C);
                uint32_t w0 = packh2(c[mt][nt][0] + b0, c[mt][nt][1] + b1);
                uint32_t w1 = packh2(c[mt][nt][2] + b0, c[mt][nt][3] + b1);
                *reinterpret_cast<uint32_t*>(Ch + (size_t)r0 * Ncols + col) = w0;
                *reinterpret_cast<uint32_t*>(Ch + (size_t)(r0 + 8) * Ncols + col) = w1;
            } else {
                float* Cf = reinterpret_cast<float*>(C);
                float2 v0 = make_float2(c[mt][nt][0] + b0, c[mt][nt][1] + b1);
                float2 v1 = make_float2(c[mt][nt][2] + b0, c[mt][nt][3] + b1);
                *reinterpret_cast<float2*>(Cf + (size_t)r0 * Ncols + col) = v0;
                *reinterpret_cast<float2*>(Cf + (size_t)(r0 + 8) * Ncols + col) = v1;
            }
        }
    }
}

// ---------------------------------------------------------------- fp32 -> fp16
__global__ void __launch_bounds__(256)
tohalf_kernel(const float* __restrict__ in, __half* __restrict__ out, size_t n4)
{
    size_t i = (size_t)blockIdx.x * blockDim.x + threadIdx.x;
    if (i >= n4) return;
    float4 v = reinterpret_cast<const float4*>(in)[i];
    uint2 o;
    o.x = packh2(v.x, v.y);
    o.y = packh2(v.z, v.w);
    reinterpret_cast<uint2*>(out)[i] = o;
}

// ---------------------------------------------------------------- transpose (+fp16)
__global__ void __launch_bounds__(256)
transpose_kernel(const float* __restrict__ in, __half* __restrict__ out,
                 int R, int Ccols)
{
    __shared__ float tile[32][33];
    int c0 = blockIdx.x * 32, r0 = blockIdx.y * 32;
    int tx = threadIdx.x & 31, ty = threadIdx.x >> 5;
    for (int i = ty; i < 32; i += 8)
        tile[i][tx] = in[(size_t)(r0 + i) * Ccols + c0 + tx];
    __syncthreads();
    for (int i = ty; i < 32; i += 8)
        out[(size_t)(c0 + i) * R + r0 + tx] = __float2half_rn(tile[tx][i]);
}

// ---------------------------------------------------------------- attention
// reads fp16 qkv -> fp32 smem, computes fp32, writes fp16 att.
__global__ void __launch_bounds__(256)
attn_kernel(const __half* __restrict__ qkv, const float* __restrict__ mask,
            __half* __restrict__ out)
{
    extern __shared__ float sh[];
    float* sq = sh;
    float* sk = sh + 8 * QPITCH;
    float* sv = sh + 16 * QPITCH;
    float* sd = sh + 24 * QPITCH;

    const int p   = blockIdx.x;
    const int tid = threadIdx.x;
    const __half* base = qkv + (size_t)p * N_TOK * INNER3;

    // 8 rows x 1536 halves = 1536 uint4 (8 halves each); 6 per thread
    for (int s = tid; s < 1536; s += 256) {
        int row = s / 192;
        int c8  = s % 192;
        uint4 raw = *reinterpret_cast<const uint4*>(base + (size_t)row * INNER3 + c8 * 8);
        const __half2* h2 = reinterpret_cast<const __half2*>(&raw);
        float2 f0 = __half22float2(h2[0]);
        float2 f1 = __half22float2(h2[1]);
        float2 f2 = __half22float2(h2[2]);
        float2 f3 = __half22float2(h2[3]);
        int col = c8 * 8;
        float* dst; int cc;
        if (col < 512)       { dst = sq + row * QPITCH; cc = col; }
        else if (col < 1024) { dst = sk + row * QPITCH; cc = col - 512; }
        else                 { dst = sv + row * QPITCH; cc = col - 1024; }
        float4 lo = make_float4(f0.x, f0.y, f1.x, f1.y);
        float4 hi = make_float4(f2.x, f2.y, f3.x, f3.y);
        *reinterpret_cast<float4*>(dst + cc)     = lo;
        *reinterpret_cast<float4*>(dst + cc + 4) = hi;
    }
    __syncthreads();

    for (int s = tid; s < 512; s += 256) {
        int h = s >> 6, i = (s >> 3) & 7, j = s & 7;
        const float4* qp = reinterpret_cast<const float4*>(&sq[i * QPITCH + h * 64]);
        const float4* kp = reinterpret_cast<const float4*>(&sk[j * QPITCH + h * 64]);
        float acc = 0.f;
#pragma unroll
        for (int d = 0; d < 16; d++) {
            float4 a = qp[d], b = kp[d];
            acc += a.x * b.x + a.y * b.y + a.z * b.z + a.w * b.w;
        }
        float m = mask[(size_t)p * 64 + i * 8 + j];
        sd[(h * 8 + i) * 8 + j] = acc * SCALE_F * m;
    }
    __syncthreads();

    if (tid < 64) {
        int h = tid >> 3, i = tid & 7;
        float* row = &sd[(h * 8 + i) * 8];
        float mx = row[0];
#pragma unroll
        for (int j = 1; j < 8; j++) mx = fmaxf(mx, row[j]);
        float e[8], sum = 0.f;
#pragma unroll
        for (int j = 0; j < 8; j++) { e[j] = __expf(row[j] - mx); sum += e[j]; }
        float inv = 1.f / sum;
#pragma unroll
        for (int j = 0; j < 8; j++) row[j] = e[j] * inv;
    }
    __syncthreads();

    __half* ob = out + (size_t)p * N_TOK * INNER;
    for (int s = tid; s < 1024; s += 256) {
        int i   = s >> 7;
        int c4  = s & 127;
        int col = c4 * 4;
        int h   = col >> 6;
        float4 acc = make_float4(0.f, 0.f, 0.f, 0.f);
#pragma unroll
        for (int j = 0; j < 8; j++) {
            float a = sd[(h * 8 + i) * 8 + j];
            float4 vv = *reinterpret_cast<const float4*>(&sv[j * QPITCH + col]);
            acc.x = fmaf(a, vv.x, acc.x);
            acc.y = fmaf(a, vv.y, acc.y);
            acc.z = fmaf(a, vv.z, acc.z);
            acc.w = fmaf(a, vv.w, acc.w);
        }
        uint2 o;
        o.x = packh2(acc.x, acc.y);
        o.y = packh2(acc.z, acc.w);
        *reinterpret_cast<uint2*>(ob + (size_t)i * INNER + col) = o;
    }
}

// ---------------------------------------------------------------- launch
extern "C" void kernel_launch(void* const* d_in, const int* in_sizes, int n_in,
                              void* d_out, int out_size)
{
    (void)in_sizes; (void)n_in; (void)out_size;
    const float* x     = (const float*)d_in[0];
    const float* mask  = (const float*)d_in[1];
    const float* w_qkv = (const float*)d_in[2];
    const float* w_out = (const float*)d_in[3];
    const float* b_out = (const float*)d_in[4];
    float* out = (float*)d_out;

    __half *qkv_p, *att_p, *xtf_p, *wqkvT_p, *woutT_p;
    cudaGetSymbolAddress((void**)&qkv_p, g_qkv);
    cudaGetSymbolAddress((void**)&att_p, g_att);
    cudaGetSymbolAddress((void**)&xtf_p, g_xtf);
    cudaGetSymbolAddress((void**)&wqkvT_p, g_wqkvT);
    cudaGetSymbolAddress((void**)&woutT_p, g_woutT);

    cudaFuncSetAttribute(gemm_f16<false, __half>,
                         cudaFuncAttributeMaxDynamicSharedMemorySize, GEMM_SMEM);
    cudaFuncSetAttribute(gemm_f16<true, float>,
                         cudaFuncAttributeMaxDynamicSharedMemorySize, GEMM_SMEM);
    const int ATTN_SMEM = (24 * QPITCH + 512) * 4;
    cudaFuncSetAttribute(attn_kernel,
                         cudaFuncAttributeMaxDynamicSharedMemorySize, ATTN_SMEM);

    const size_t n4 = (size_t)M_ROWS * DIM / 4;
    tohalf_kernel<<<(unsigned)((n4 + 255) / 256), 256>>>(x, xtf_p, n4);
    transpose_kernel<<<dim3(INNER3 / 32, DIM / 32), 256>>>(w_qkv, wqkvT_p, DIM, INNER3);
    transpose_kernel<<<dim3(INNER  / 32, DIM / 32), 256>>>(w_out, woutT_p, DIM, INNER);

    // 1) qkv = x @ w_qkv  (fp16 out)
    gemm_f16<false, __half><<<dim3(INNER3 / BN, M_ROWS / BM), 256, GEMM_SMEM>>>(
        xtf_p, wqkvT_p, nullptr, qkv_p, INNER3);
    // 2) attention (fp16 in/out, fp32 math)
    attn_kernel<<<N_PIX, 256, ATTN_SMEM>>>(qkv_p, mask, att_p);
    // 3) out = att @ w_out + b_out  (fp32 out)
    gemm_f16<true, float><<<dim3(INNER / BN, M_ROWS / BM), 256, GEMM_SMEM>>>(
        att_p, woutT_p, b_out, out, INNER);
}

// round 10
// speedup vs baseline: 1.9650x; 1.0096x over previous
#include <cuda_runtime.h>
#include <cuda_fp16.h>
#include <cstdint>
#include <math.h>

// ---------------------------------------------------------------- constants
#define N_PIX     8192
#define N_TOK     8
#define DIM       512
#define INNER     512
#define INNER3    1536
#define SCALE_F   0.125f
#define M_ROWS    65536

// GEMM tiling (fp16 m16n8k16)
#define BM     128
#define BN     128
#define BK     32                       // halves of K per tile (2 k16 chunks)
#define STAGES 4
#define TK     (DIM / BK)               // 16 K-tiles
#define ROWB   80                       // bytes per smem row (40 halves)
#define TILE_BYTES  (128 * ROWB)        // 10240 B per operand
#define STAGE_BYTES (2 * TILE_BYTES)    // 20480 B
#define GEMM_SMEM   (STAGES * STAGE_BYTES)  // 81920 B

#define QPITCH 516

// Scratch (__device__ globals per allocation rules)
__device__ __half g_qkv[(size_t)M_ROWS * INNER3];
__device__ __half g_att[(size_t)M_ROWS * INNER];
__device__ __half g_xtf[(size_t)M_ROWS * DIM];
__device__ __half g_wqkvT[(size_t)INNER3 * DIM];
__device__ __half g_woutT[(size_t)INNER * DIM];

// ---------------------------------------------------------------- helpers
__device__ __forceinline__ uint32_t smem_u32(const void* p) {
    uint32_t a;
    asm("{ .reg .u64 t; cvta.to.shared.u64 t, %1; cvt.u32.u64 %0, t; }"
        : "=r"(a) : "l"(p));
    return a;
}
__device__ __forceinline__ void cp16(uint32_t dst, const void* src) {
    asm volatile("cp.async.cg.shared.global [%0], [%1], 16;"
                 :: "r"(dst), "l"(src));
}
__device__ __forceinline__ void cp_commit() {
    asm volatile("cp.async.commit_group;" ::: "memory");
}
template <int N> __device__ __forceinline__ void cp_wait() {
    asm volatile("cp.async.wait_group %0;" :: "n"(N) : "memory");
}
__device__ __forceinline__ void ldmx4(uint32_t* r, uint32_t addr) {
    asm volatile("ldmatrix.sync.aligned.m8n8.x4.shared.b16 {%0,%1,%2,%3}, [%4];"
                 : "=r"(r[0]), "=r"(r[1]), "=r"(r[2]), "=r"(r[3]) : "r"(addr));
}
__device__ __forceinline__ void mma_f16(float* c, uint32_t a0, uint32_t a1,
                                        uint32_t a2, uint32_t a3,
                                        uint32_t b0, uint32_t b1) {
    asm volatile(
        "mma.sync.aligned.m16n8k16.row.col.f32.f16.f16.f32 "
        "{%0,%1,%2,%3}, {%4,%5,%6,%7}, {%8,%9}, {%0,%1,%2,%3};"
        : "+f"(c[0]), "+f"(c[1]), "+f"(c[2]), "+f"(c[3])
        : "r"(a0), "r"(a1), "r"(a2), "r"(a3), "r"(b0), "r"(b1));
}
__device__ __forceinline__ uint32_t packh2(float x, float y) {
    __half2 h = __floats2half2_rn(x, y);
    return *reinterpret_cast<uint32_t*>(&h);
}

struct FragSet {
    uint32_t a[4][4];
    uint32_t b[2][4];
};

// ---------------------------------------------------------------- fp16 GEMM
template <bool BIAS, typename OutT>
__global__ void __launch_bounds__(256, 2)
gemm_f16(const __half* __restrict__ A, const __half* __restrict__ Bt,
         const float* __restrict__ bias, OutT* __restrict__ C, int Ncols)
{
    extern __shared__ char smem[];
    const int tid  = threadIdx.x;
    const int wid  = tid >> 5, lane = tid & 31;
    const int g    = lane >> 2, tig = lane & 3;
    const int wm   = (wid >> 2) * 64;
    const int wn   = (wid & 3) * 32;
    const int bm   = blockIdx.y * BM;
    const int bn   = blockIdx.x * BN;
    const uint32_t sbase = smem_u32(smem);

    const int lm = lane >> 3, lr = lane & 7;
    const uint32_t aLane = (uint32_t)(((lm & 1) * 8 + lr) * ROWB + (lm >> 1) * 16);
    const uint32_t bLane = (uint32_t)(((lm >> 1) * 8 + lr) * ROWB + (lm & 1) * 16);
    const uint32_t aBase = (uint32_t)(wm * ROWB) + aLane;
    const uint32_t bBase = (uint32_t)(TILE_BYTES + wn * ROWB) + bLane;

    float c[4][4][4];
#pragma unroll
    for (int i = 0; i < 4; i++)
#pragma unroll
        for (int j = 0; j < 4; j++)
#pragma unroll
            for (int q = 0; q < 4; q++) c[i][j][q] = 0.f;

    auto load_tile = [&](int t, int s) {
        uint32_t st = sbase + (uint32_t)(s * STAGE_BYTES);
        const __half* Ab = A + (size_t)bm * DIM + t * BK;
#pragma unroll
        for (int i = 0; i < 2; i++) {
            int id = tid + i * 256;
            int r = id >> 2, ck = id & 3;
            cp16(st + (uint32_t)(r * ROWB + ck * 16),
                 Ab + (size_t)r * DIM + ck * 8);
        }
        uint32_t stB = st + TILE_BYTES;
        const __half* Bb = Bt + (size_t)bn * DIM + t * BK;
#pragma unroll
        for (int i = 0; i < 2; i++) {
            int id = tid + i * 256;
            int r = id >> 2, ck = id & 3;
            cp16(stB + (uint32_t)(r * ROWB + ck * 16),
                 Bb + (size_t)r * DIM + ck * 8);
        }
    };

    auto ld_frags = [&](FragSet& f, uint32_t stage, uint32_t ko) {
#pragma unroll
        for (int mt = 0; mt < 4; mt++)
            ldmx4(f.a[mt], stage + aBase + (uint32_t)(mt * 16 * ROWB) + ko);
#pragma unroll
        for (int p = 0; p < 2; p++)
            ldmx4(f.b[p], stage + bBase + (uint32_t)(p * 16 * ROWB) + ko);
    };

    auto mma_set = [&](const FragSet& f) {
#pragma unroll
        for (int mt = 0; mt < 4; mt++)
#pragma unroll
            for (int nt = 0; nt < 4; nt++) {
                const uint32_t* bb = &f.b[nt >> 1][(nt & 1) * 2];
                mma_f16(c[mt][nt], f.a[mt][0], f.a[mt][1], f.a[mt][2],
                        f.a[mt][3], bb[0], bb[1]);
            }
    };

    // prologue: 3 tiles in flight
    load_tile(0, 0); cp_commit();
    load_tile(1, 1); cp_commit();
    load_tile(2, 2); cp_commit();

    FragSet F, G;
    cp_wait<2>();                 // tile 0 resident
    __syncthreads();
    ld_frags(F, sbase, 0);        // chunk0 of tile 0

    for (int t = 0; t < TK; t++) {
        cp_wait<1>();             // tiles <= t+1 resident
        __syncthreads();          // all warps done with tile t-1 frag reads
        if (t + 3 < TK) load_tile(t + 3, (t + 3) % STAGES);
        cp_commit();

        const uint32_t scur = sbase + (uint32_t)((t % STAGES) * STAGE_BYTES);
        const uint32_t snxt = sbase + (uint32_t)(((t + 1) % STAGES) * STAGE_BYTES);

        ld_frags(G, scur, 32);                       // chunk1 of tile t
        mma_set(F);                                  // chunk0 of tile t
        ld_frags(F, (t + 1 < TK) ? snxt : scur, 0);  // chunk0 of tile t+1
        mma_set(G);                                  // chunk1 of tile t
    }

#pragma unroll
    for (int mt = 0; mt < 4; mt++) {
#pragma unroll
        for (int nt = 0; nt < 4; nt++) {
            int col = bn + wn + nt * 8 + 2 * tig;
            float b0 = 0.f, b1 = 0.f;
            if (BIAS) { b0 = bias[col]; b1 = bias[col + 1]; }
            int r0 = bm + wm + mt * 16 + g;
            if (sizeof(OutT) == 2) {
                __half* Ch = reinterpret_cast<__half*>(C);
                uint32_t w0 = packh2(c[mt][nt][0] + b0, c[mt][nt][1] + b1);
                uint32_t w1 = packh2(c[mt][nt][2] + b0, c[mt][nt][3] + b1);
                *reinterpret_cast<uint32_t*>(Ch + (size_t)r0 * Ncols + col) = w0;
                *reinterpret_cast<uint32_t*>(Ch + (size_t)(r0 + 8) * Ncols + col) = w1;
            } else {
                float* Cf = reinterpret_cast<float*>(C);
                float2 v0 = make_float2(c[mt][nt][0] + b0, c[mt][nt][1] + b1);
                float2 v1 = make_float2(c[mt][nt][2] + b0, c[mt][nt][3] + b1);
                *reinterpret_cast<float2*>(Cf + (size_t)r0 * Ncols + col) = v0;
                *reinterpret_cast<float2*>(Cf + (size_t)(r0 + 8) * Ncols + col) = v1;
            }
        }
    }
}

// ---------------------------------------------------------------- fp32 -> fp16
__global__ void __launch_bounds__(256)
tohalf_kernel(const float* __restrict__ in, __half* __restrict__ out, size_t n4)
{
    size_t i = (size_t)blockIdx.x * blockDim.x + threadIdx.x;
    if (i >= n4) return;
    float4 v = reinterpret_cast<const float4*>(in)[i];
    uint2 o;
    o.x = packh2(v.x, v.y);
    o.y = packh2(v.z, v.w);
    reinterpret_cast<uint2*>(out)[i] = o;
}

// ---------------------------------------------------------------- transpose (+fp16)
__global__ void __launch_bounds__(256)
transpose_kernel(const float* __restrict__ in, __half* __restrict__ out,
                 int R, int Ccols)
{
    __shared__ float tile[32][33];
    int c0 = blockIdx.x * 32, r0 = blockIdx.y * 32;
    int tx = threadIdx.x & 31, ty = threadIdx.x >> 5;
    for (int i = ty; i < 32; i += 8)
        tile[i][tx] = in[(size_t)(r0 + i) * Ccols + c0 + tx];
    __syncthreads();
    for (int i = ty; i < 32; i += 8)
        out[(size_t)(c0 + i) * R + r0 + tx] = __float2half_rn(tile[tx][i]);
}

// ---------------------------------------------------------------- attention
__global__ void __launch_bounds__(256)
attn_kernel(const __half* __restrict__ qkv, const float* __restrict__ mask,
            __half* __restrict__ out)
{
    extern __shared__ float sh[];
    float* sq = sh;
    float* sk = sh + 8 * QPITCH;
    float* sv = sh + 16 * QPITCH;
    float* sd = sh + 24 * QPITCH;

    const int p   = blockIdx.x;
    const int tid = threadIdx.x;
    const __half* base = qkv + (size_t)p * N_TOK * INNER3;

    for (int s = tid; s < 1536; s += 256) {
        int row = s / 192;
        int c8  = s % 192;
        uint4 raw = *reinterpret_cast<const uint4*>(base + (size_t)row * INNER3 + c8 * 8);
        const __half2* h2 = reinterpret_cast<const __half2*>(&raw);
        float2 f0 = __half22float2(h2[0]);
        float2 f1 = __half22float2(h2[1]);
        float2 f2 = __half22float2(h2[2]);
        float2 f3 = __half22float2(h2[3]);
        int col = c8 * 8;
        float* dst; int cc;
        if (col < 512)       { dst = sq + row * QPITCH; cc = col; }
        else if (col < 1024) { dst = sk + row * QPITCH; cc = col - 512; }
        else                 { dst = sv + row * QPITCH; cc = col - 1024; }
        *reinterpret_cast<float4*>(dst + cc)     = make_float4(f0.x, f0.y, f1.x, f1.y);
        *reinterpret_cast<float4*>(dst + cc + 4) = make_float4(f2.x, f2.y, f3.x, f3.y);
    }
    __syncthreads();

    for (int s = tid; s < 512; s += 256) {
        int h = s >> 6, i = (s >> 3) & 7, j = s & 7;
        const float4* qp = reinterpret_cast<const float4*>(&sq[i * QPITCH + h * 64]);
        const float4* kp = reinterpret_cast<const float4*>(&sk[j * QPITCH + h * 64]);
        float acc = 0.f;
#pragma unroll
        for (int d = 0; d < 16; d++) {
            float4 a = qp[d], b = kp[d];
            acc += a.x * b.x + a.y * b.y + a.z * b.z + a.w * b.w;
        }
        float m = mask[(size_t)p * 64 + i * 8 + j];
        sd[(h * 8 + i) * 8 + j] = acc * SCALE_F * m;
    }
    __syncthreads();

    if (tid < 64) {
        int h = tid >> 3, i = tid & 7;
        float* row = &sd[(h * 8 + i) * 8];
        float mx = row[0];
#pragma unroll
        for (int j = 1; j < 8; j++) mx = fmaxf(mx, row[j]);
        float e[8], sum = 0.f;
#pragma unroll
        for (int j = 0; j < 8; j++) { e[j] = __expf(row[j] - mx); sum += e[j]; }
        float inv = 1.f / sum;
#pragma unroll
        for (int j = 0; j < 8; j++) row[j] = e[j] * inv;
    }
    __syncthreads();

    __half* ob = out + (size_t)p * N_TOK * INNER;
    for (int s = tid; s < 1024; s += 256) {
        int i   = s >> 7;
        int c4  = s & 127;
        int col = c4 * 4;
        int h   = col >> 6;
        float4 acc = make_float4(0.f, 0.f, 0.f, 0.f);
#pragma unroll
        for (int j = 0; j < 8; j++) {
            float a = sd[(h * 8 + i) * 8 + j];
            float4 vv = *reinterpret_cast<const float4*>(&sv[j * QPITCH + col]);
            acc.x = fmaf(a, vv.x, acc.x);
            acc.y = fmaf(a, vv.y, acc.y);
            acc.z = fmaf(a, vv.z, acc.z);
            acc.w = fmaf(a, vv.w, acc.w);
        }
        uint2 o;
        o.x = packh2(acc.x, acc.y);
        o.y = packh2(acc.z, acc.w);
        *reinterpret_cast<uint2*>(ob + (size_t)i * INNER + col) = o;
    }
}

// ---------------------------------------------------------------- launch
extern "C" void kernel_launch(void* const* d_in, const int* in_sizes, int n_in,
                              void* d_out, int out_size)
{
    (void)in_sizes; (void)n_in; (void)out_size;
    const float* x     = (const float*)d_in[0];
    const float* mask  = (const float*)d_in[1];
    const float* w_qkv = (const float*)d_in[2];
    const float* w_out = (const float*)d_in[3];
    const float* b_out = (const float*)d_in[4];
    float* out = (float*)d_out;

    __half *qkv_p, *att_p, *xtf_p, *wqkvT_p, *woutT_p;
    cudaGetSymbolAddress((void**)&qkv_p, g_qkv);
    cudaGetSymbolAddress((void**)&att_p, g_att);
    cudaGetSymbolAddress((void**)&xtf_p, g_xtf);
    cudaGetSymbolAddress((void**)&wqkvT_p, g_wqkvT);
    cudaGetSymbolAddress((void**)&woutT_p, g_woutT);

    cudaFuncSetAttribute(gemm_f16<false, __half>,
                         cudaFuncAttributeMaxDynamicSharedMemorySize, GEMM_SMEM);
    cudaFuncSetAttribute(gemm_f16<true, float>,
                         cudaFuncAttributeMaxDynamicSharedMemorySize, GEMM_SMEM);
    const int ATTN_SMEM = (24 * QPITCH + 512) * 4;
    cudaFuncSetAttribute(attn_kernel,
                         cudaFuncAttributeMaxDynamicSharedMemorySize, ATTN_SMEM);

    const size_t n4 = (size_t)M_ROWS * DIM / 4;
    tohalf_kernel<<<(unsigned)((n4 + 255) / 256), 256>>>(x, xtf_p, n4);
    transpose_kernel<<<dim3(INNER3 / 32, DIM / 32), 256>>>(w_qkv, wqkvT_p, DIM, INNER3);
    transpose_kernel<<<dim3(INNER  / 32, DIM / 32), 256>>>(w_out, woutT_p, DIM, INNER);

    gemm_f16<false, __half><<<dim3(INNER3 / BN, M_ROWS / BM), 256, GEMM_SMEM>>>(
        xtf_p, wqkvT_p, nullptr, qkv_p, INNER3);
    attn_kernel<<<N_PIX, 256, ATTN_SMEM>>>(qkv_p, mask, att_p);
    gemm_f16<true, float><<<dim3(INNER / BN, M_ROWS / BM), 256, GEMM_SMEM>>>(
        att_p, woutT_p, b_out, out, INNER);
}